// round 8
// baseline (speedup 1.0000x reference)
#include <cuda_runtime.h>
#include <cuda_bf16.h>
#include <cstdint>

// Problem constants (reference: TRACK_SIZE=16, C=240 -> 15 tracks).
#define C_TOT   240
#define ROW_F4  60          // float4 per output/input row
#define SROW    61          // padded smem row stride (float4) to break conflicts
#define TJ      32          // tile rows (output rows for phase A, input rows for scatter)
#define TEXT    48          // tile + halo rows loaded into smem (covers shifts <= 16)
#define NTHR    480

// Hybrid input-major kernel.
//  Phase 0: load input rows [j0, j0+48) (clipped to L) into smem, coalesced.
//  Phase A: (non-edge tiles) write output rows [j0, j0+32), tracks 0-5
//           (shifts 0,1,2,4,8,16 < 48 -> sources are in smem) as contiguous
//           384B runs: full 128B lines, one DRAM page visit per row.
//  Phase B: scatter tracks 6-14 (and, for edge tiles / fallback, tracks 0-5)
//           exactly as the proven R5 kernel, sourced from smem.
// Forward map: out[j][t] = x[((j+shift_t)%P)%L][t]; the scatter enumerates,
// for input row r: vv = r + m*L (vv < P) -> j = vv - shift (and j + P).
__global__ __launch_bounds__(NTHR, 4) void rc_hybrid_kernel(
    const float4* __restrict__ x,       // (B, N, 60) float4
    const int*    __restrict__ lengths, // (B,)
    float4*       __restrict__ out,     // (B, max_len, 60) float4
    int B, int N, int max_len)
{
    __shared__ __align__(16) float4 sm[TEXT * SROW];   // ~46.8 KB

    const int b  = blockIdx.z;
    const int L  = __ldg(lengths + b);
    const int j0 = blockIdx.x * TJ;
    if (j0 >= L) return;   // no input rows here; such output rows are edge
                           // tiles covered by other CTAs' scatter.

    int minL = __ldg(lengths);
    #pragma unroll 4
    for (int i = 1; i < B; ++i) minL = min(minL, __ldg(lengths + i));
    const int P = 3 * minL;

    // Phase A is safe only if the P-wrap can never land a low-track chunk
    // inside [0, max_len) (always true for this data: P >> max_len).
    const bool phaseA_en = (P - 16) >= max_len;
    const bool phaseA    = phaseA_en && (j0 + TEXT - 1 < L);

    const int q   = threadIdx.x;               // 0..59
    const int ty  = threadIdx.y;               // 0..7
    const int tid = ty * ROW_F4 + q;           // 0..479

    // ---- Phase 0: coalesced smem fill ----
    const int rows_load = min(phaseA ? TEXT : TJ, L - j0);
    const float4* __restrict__ src = x + ((size_t)b * N + j0) * ROW_F4;
    const int total_ld = rows_load * ROW_F4;
    for (int i = tid; i < total_ld; i += NTHR) {
        const int row = i / ROW_F4;
        const int col = i - row * ROW_F4;
        sm[row * SROW + col] = __ldg(src + i);
    }
    __syncthreads();

    float4* __restrict__ outb = out + (size_t)b * max_len * ROW_F4;

    // ---- Phase A: tracks 0-5 as contiguous 384B full-line runs ----
    if (phaseA) {
        const int jmax  = min(TJ, max_len - j0);
        const int total = jmax * 24;           // 24 float4 = tracks 0-5
        for (int i = tid; i < total; i += NTHR) {
            const int jr = i / 24;
            const int c  = i - jr * 24;        // f4 column 0..23
            const int t  = c >> 2;
            const int s  = (1 << t) >> 1;      // 0,1,2,4,8,16
            outb[(size_t)(j0 + jr) * ROW_F4 + c] = sm[(jr + s) * SROW + c];
        }
    }

    // ---- Phase B: scatter (tracks >=6 always; tracks 0-5 only where the
    //      target tile has no phase A) ----
    const int t     = q >> 2;
    const int shift = (1u << t) >> 1;
    const bool lowtrack = (t < 6) && phaseA_en;
    const int nrows = min(TJ, L - j0);
    float4* __restrict__ dst = outb + q;

    #pragma unroll
    for (int k = 0; k < 4; ++k) {
        const int rl = ty + 8 * k;
        if (rl >= nrows) continue;
        const float4 v = sm[rl * SROW + q];
        const int r = j0 + rl;
        #pragma unroll
        for (int m = 0; m < 3; ++m) {
            const int vv = r + m * L;
            if (vv < P) {
                const int j = vv - shift;
                if (j >= 0 && j < max_len &&
                    (!lowtrack || ((j & ~(TJ - 1)) + TEXT - 1) >= L))
                    dst[(size_t)j * ROW_F4] = v;
                const int j2 = j + P;          // P-wrap generality
                if (j2 >= 0 && j2 < max_len &&
                    (!lowtrack || ((j2 & ~(TJ - 1)) + TEXT - 1) >= L))
                    dst[(size_t)j2 * ROW_F4] = v;
            }
        }
    }
}

extern "C" void kernel_launch(void* const* d_in, const int* in_sizes, int n_in,
                              void* d_out, int out_size) {
    const float* x       = (const float*)d_in[0];
    const int*   lengths = (const int*)d_in[1];
    float*       out     = (float*)d_out;

    const int B = in_sizes[1];                    // 8
    const int N = in_sizes[0] / (B * C_TOT);      // 16384
    const int max_len = out_size / (B * C_TOT);   // max(lengths)

    dim3 blk(ROW_F4, 8, 1);                       // 480 threads
    dim3 grid((max_len + TJ - 1) / TJ, 1, B);     // (512,1,8)
    rc_hybrid_kernel<<<grid, blk>>>((const float4*)x, lengths, (float4*)out,
                                    B, N, max_len);
}

// round 9
// speedup vs baseline: 1.0520x; 1.0520x over previous
#include <cuda_runtime.h>
#include <cuda_bf16.h>
#include <cstdint>

// Problem constants (reference: TRACK_SIZE=16, C=240 -> 15 tracks).
#define C_TOT   240
#define ROW_F4  60          // float4 per row
#define TJ      64          // output rows per CTA
#define RPB     8           // rows per warp batch (32 lanes = 8 rows x 4 chunks)
#define NBATCH  (TJ / RPB)  // 8 batches, processed in pairs for MLP

// Warp-per-track gather: block = 480 threads = 15 warps, warp w owns track w.
// lane -> (rl = lane/4 row-in-batch, qc = lane%4 chunk-in-track).
// CTA writes output rows [j0, j0+64) completely (all tracks) so every output
// cache line / DRAM page is assembled by one CTA in a tight window.
// out[j][t] = x[((j + shift_t) % P) % L][t], P = 3*min(lengths).
__global__ __launch_bounds__(480, 4) void rc_gather_wpt_kernel(
    const float4* __restrict__ x,       // (B, N, 60) float4
    const int*    __restrict__ lengths, // (B,)
    float4*       __restrict__ out,     // (B, max_len, 60) float4
    int B, int N, int max_len)
{
    const int tid  = threadIdx.x;
    const int w    = tid >> 5;          // 0..14 : track
    const int lane = tid & 31;
    const int rl   = lane >> 2;         // 0..7  : row within batch
    const int qc   = lane & 3;          // 0..3  : float4 chunk within track

    const int b  = blockIdx.z;
    const int j0 = blockIdx.x * TJ;
    if (j0 >= max_len) return;

    // min(lengths): B tiny; L1-hit broadcast loads.
    int minL = __ldg(lengths);
    #pragma unroll 4
    for (int i = 1; i < B; ++i) minL = min(minL, __ldg(lengths + i));
    const int P = 3 * minL;
    const int L = __ldg(lengths + b);

    const int shift = (1u << w) >> 1;   // 0,1,2,4,...,2^13

    // Base row index for this lane's first batch, pre-wrapped.
    int v0 = j0 + rl + shift;
    while (v0 >= P) v0 -= P;

    const float4* __restrict__ src = x + (size_t)b * N * ROW_F4 + (w << 2) + qc;
    float4* __restrict__ dst = out + ((size_t)b * max_len + j0 + rl) * ROW_F4
                                   + (w << 2) + qc;

    const int rem = max_len - (j0 + rl);          // rows this lane may write

    if (rem >= TJ && v0 + TJ <= P) {
        // Fast path: pairs of batches -> 2 loads in flight, then 2 stores.
        #pragma unroll
        for (int h = 0; h < NBATCH / 2; ++h) {
            float4 va, vb;
            {
                int r = v0 + (2 * h) * RPB;
                while (r >= L) r -= L;
                va = __ldg(src + (size_t)r * ROW_F4);
            }
            {
                int r = v0 + (2 * h + 1) * RPB;
                while (r >= L) r -= L;
                vb = __ldg(src + (size_t)r * ROW_F4);
            }
            dst[(size_t)(2 * h) * RPB * ROW_F4]     = va;
            dst[(size_t)(2 * h + 1) * RPB * ROW_F4] = vb;
        }
    } else {
        // General / tail path.
        for (int p = 0; p < NBATCH; ++p) {
            const int joff = p * RPB;
            if (joff >= rem) break;
            int v = v0 + joff;
            while (v >= P) v -= P;
            int r = v;
            while (r >= L) r -= L;
            dst[(size_t)joff * ROW_F4] = __ldg(src + (size_t)r * ROW_F4);
        }
    }
}

extern "C" void kernel_launch(void* const* d_in, const int* in_sizes, int n_in,
                              void* d_out, int out_size) {
    const float* x       = (const float*)d_in[0];
    const int*   lengths = (const int*)d_in[1];
    float*       out     = (float*)d_out;

    const int B = in_sizes[1];                    // 8
    const int N = in_sizes[0] / (B * C_TOT);      // 16384
    const int max_len = out_size / (B * C_TOT);   // max(lengths)

    dim3 blk(480, 1, 1);                          // 15 warps = 15 tracks
    dim3 grid((max_len + TJ - 1) / TJ, 1, B);     // (256,1,8)
    rc_gather_wpt_kernel<<<grid, blk>>>((const float4*)x, lengths, (float4*)out,
                                        B, N, max_len);
}

// round 10
// speedup vs baseline: 1.1087x; 1.0539x over previous
#include <cuda_runtime.h>
#include <cuda_bf16.h>
#include <cstdint>

// Problem constants (reference: TRACK_SIZE=16, C=240 -> 15 tracks).
#define C_TOT   240
#define ROW32   30          // 32B (8-float) chunks per row
#define TJ      32          // input rows per CTA tile
#define TY      8           // blockDim.y

// 256-bit global load (evict-normal, non-coherent) / store, sm_103a.
__device__ __forceinline__ void ldg256(const float* p, float* f) {
    asm volatile("ld.global.nc.v8.f32 {%0,%1,%2,%3,%4,%5,%6,%7}, [%8];"
                 : "=f"(f[0]), "=f"(f[1]), "=f"(f[2]), "=f"(f[3]),
                   "=f"(f[4]), "=f"(f[5]), "=f"(f[6]), "=f"(f[7])
                 : "l"(p));
}
__device__ __forceinline__ void stg256(float* p, const float* f) {
    asm volatile("st.global.v8.f32 [%0], {%1,%2,%3,%4,%5,%6,%7,%8};"
                 :: "l"(p),
                    "f"(f[0]), "f"(f[1]), "f"(f[2]), "f"(f[3]),
                    "f"(f[4]), "f"(f[5]), "f"(f[6]), "f"(f[7])
                 : "memory");
}

// Input-major scatter (champion R5 structure) at 32B/lane granularity:
// CTA reads input rows [r0, r0+32) fully coalesced (LDG.256; rows >= L
// skipped), then scatters each 32B chunk to its 1-3 output positions.
// Forward map: out[j][t] = x[((j+shift_t)%P)%L][t]; inverse: for vv in
// {r, r+L, r+2L} with vv<P: j = vv-shift (and j+P for the P-wrap case).
__global__ __launch_bounds__(240, 6) void rc_scatter256_kernel(
    const float* __restrict__ x,        // (B, N, 240)
    const int*   __restrict__ lengths,  // (B,)
    float*       __restrict__ out,      // (B, max_len, 240)
    int B, int N, int max_len)
{
    const int b  = blockIdx.z;
    const int L  = __ldg(lengths + b);
    const int r0 = blockIdx.x * TJ;
    if (r0 >= L) return;                 // rows >= L are never used

    // min(lengths): B tiny; L1-hit broadcast loads.
    int minL = __ldg(lengths);
    #pragma unroll 4
    for (int i = 1; i < B; ++i) minL = min(minL, __ldg(lengths + i));
    const int P = 3 * minL;

    const int q2 = threadIdx.x;          // 0..29 : 32B chunk within row
    const int ty = threadIdx.y;          // 0..7
    const int shift = (1u << (q2 >> 1)) >> 1;   // track = q2/2

    const float* __restrict__ src = x + ((size_t)b * N + r0) * C_TOT + q2 * 8;
    float* __restrict__ dst = out + (size_t)b * max_len * C_TOT + q2 * 8;

    // Two batches of 2 rows: 2 LDG.256 in flight, then scatter, repeat.
    #pragma unroll
    for (int h = 0; h < 2; ++h) {
        float fa[8], fb[8];
        const int rla = ty + 16 * h;          // rows ty, ty+16
        const int rlb = rla + 8;              // rows ty+8, ty+24
        const int ra = r0 + rla, rb = r0 + rlb;
        const bool oka = ra < L, okb = rb < L;
        if (oka) ldg256(src + (size_t)rla * C_TOT, fa);
        if (okb) ldg256(src + (size_t)rlb * C_TOT, fb);

        #pragma unroll
        for (int s = 0; s < 2; ++s) {
            const int r = s ? rb : ra;
            const float* f = s ? fb : fa;
            if (!(s ? okb : oka)) continue;
            #pragma unroll
            for (int m = 0; m < 3; ++m) {
                const int vv = r + m * L;
                if (vv < P) {
                    const int j = vv - shift;
                    if (j >= 0 && j < max_len)
                        stg256(dst + (size_t)j * C_TOT, f);
                    const int j2 = j + P;     // P-wrap generality
                    if (j2 >= 0 && j2 < max_len)
                        stg256(dst + (size_t)j2 * C_TOT, f);
                }
            }
        }
    }
}

extern "C" void kernel_launch(void* const* d_in, const int* in_sizes, int n_in,
                              void* d_out, int out_size) {
    const float* x       = (const float*)d_in[0];
    const int*   lengths = (const int*)d_in[1];
    float*       out     = (float*)d_out;

    const int B = in_sizes[1];                    // 8
    const int N = in_sizes[0] / (B * C_TOT);      // 16384
    const int max_len = out_size / (B * C_TOT);   // max(lengths)

    dim3 blk(ROW32, TY, 1);                       // 240 threads
    dim3 grid((N + TJ - 1) / TJ, 1, B);           // (512,1,8); tail CTAs exit
    rc_scatter256_kernel<<<grid, blk>>>(x, lengths, out, B, N, max_len);
}